// round 16
// baseline (speedup 1.0000x reference)
#include <cuda_runtime.h>
#include <cuda_bf16.h>
#include <cstdint>

#define EB    1024
#define HN    16
#define DH    64
#define BB    2
#define SS    2048
#define MT    (BB*SS)       // 4096
#define E3    (3*EB)        // 3072

typedef unsigned long long u64;

// Scratch (device globals — allocation is forbidden)
__device__ float g_qkv[(size_t)MT * E3];        // [token][3E]
__device__ float g_attn2[2][(size_t)MT * EB];   // PV split-K partial outputs
__device__ float g_part[(size_t)BB * HN * SS * 16];

// ---------------- HMMA (mma.sync) helpers — sm_80-era PTX ----------------
__device__ __forceinline__ uint32_t smem_u32(const void* p) {
    uint32_t a;
    asm("{ .reg .u64 t; cvta.to.shared.u64 t, %1; cvt.u32.u64 %0, t; }" : "=r"(a) : "l"(p));
    return a;
}
#define LDSM_X4(r, addr) \
    asm volatile("ldmatrix.sync.aligned.m8n8.x4.shared.b16 {%0,%1,%2,%3}, [%4];" \
        : "=r"((r)[0]), "=r"((r)[1]), "=r"((r)[2]), "=r"((r)[3]) : "r"(addr))
#define LDSM_X2(r, addr) \
    asm volatile("ldmatrix.sync.aligned.m8n8.x2.shared.b16 {%0,%1}, [%2];" \
        : "=r"((r)[0]), "=r"((r)[1]) : "r"(addr))
#define LDSM_X2_TRANS(r, addr) \
    asm volatile("ldmatrix.sync.aligned.m8n8.x2.trans.shared.b16 {%0,%1}, [%2];" \
        : "=r"((r)[0]), "=r"((r)[1]) : "r"(addr))
#define MMA_BF16(d, a, b) \
    asm volatile("mma.sync.aligned.m16n8k16.row.col.f32.bf16.bf16.f32 " \
        "{%0,%1,%2,%3}, {%4,%5,%6,%7}, {%8,%9}, {%0,%1,%2,%3};" \
        : "+f"((d)[0]), "+f"((d)[1]), "+f"((d)[2]), "+f"((d)[3]) \
        : "r"((a)[0]), "r"((a)[1]), "r"((a)[2]), "r"((a)[3]), \
          "r"((b)[0]), "r"((b)[1]))

// split two fp32 into bf16-hi pair and bf16-lo pair (packed u32: lo half = x0)
__device__ __forceinline__ void split2(float x0, float x1, uint32_t& hi2, uint32_t& lo2) {
    asm("cvt.rn.bf16x2.f32 %0, %1, %2;" : "=r"(hi2) : "f"(x1), "f"(x0));
    float h0 = __uint_as_float(hi2 << 16);
    float h1 = __uint_as_float(hi2 & 0xFFFF0000u);
    float r0 = x0 - h0, r1 = x1 - h1;
    asm("cvt.rn.bf16x2.f32 %0, %1, %2;" : "=r"(lo2) : "f"(r1), "f"(r0));
}

template<int W>
__device__ __forceinline__ void store_split(uint16_t (*H)[W], uint16_t (*L)[W],
                                            int r, int c4, float4 v) {
    uint32_t h0, l0, h1, l1;
    split2(v.x, v.y, h0, l0); split2(v.z, v.w, h1, l1);
    *(uint32_t*)&H[r][c4 * 4]     = h0; *(uint32_t*)&H[r][c4 * 4 + 2] = h1;
    *(uint32_t*)&L[r][c4 * 4]     = l0; *(uint32_t*)&L[r][c4 * 4 + 2] = l1;
}

#define SC_SMEM (4 * 128 * 72 * 2)     // 73728 bytes (scores whole-K tiles)

// =====================================================================
// HMMA GEMM: C[M,N] = (A [+ A2]) [M,K] @ B[N,K]^T + bias[N]
// CTA 128x128, BK=32, 8 warps (2m x 4n), register-prefetch pipelined.
// DUAL=true sums two A buffers at load time (PV split-K merge).
// =====================================================================
template<bool DUAL>
__global__ __launch_bounds__(256, 2) void mma_gemm_bias_nt(
    const float* __restrict__ A, const float* __restrict__ A2,
    const float* __restrict__ B,
    const float* __restrict__ bias, float* __restrict__ C,
    int M, int N, int K)
{
    __shared__ __align__(16) uint16_t Ah[128][40];
    __shared__ __align__(16) uint16_t Al[128][40];
    __shared__ __align__(16) uint16_t Bh[128][40];
    __shared__ __align__(16) uint16_t Bl[128][40];

    const int tid = threadIdx.x;
    const int lane = tid & 31, wid = tid >> 5;
    const int warp_m = wid >> 2, warp_n = wid & 3;
    const int row0 = blockIdx.y * 128, col0 = blockIdx.x * 128;
    const int lr = tid >> 3, lc4 = tid & 7;

    float acc[4][4][4];
    #pragma unroll
    for (int mi = 0; mi < 4; mi++)
        #pragma unroll
        for (int ni = 0; ni < 4; ni++)
            #pragma unroll
            for (int f = 0; f < 4; f++) acc[mi][ni][f] = 0.0f;

    float4 pa[4], pb[4];
    #pragma unroll
    for (int i = 0; i < 4; i++) {
        int r = lr + i * 32;
        pa[i] = *(const float4*)&A[(size_t)(row0 + r) * K + lc4 * 4];
        if (DUAL) {
            float4 q = *(const float4*)&A2[(size_t)(row0 + r) * K + lc4 * 4];
            pa[i].x += q.x; pa[i].y += q.y; pa[i].z += q.z; pa[i].w += q.w;
        }
        pb[i] = *(const float4*)&B[(size_t)(col0 + r) * K + lc4 * 4];
    }

    for (int k0 = 0; k0 < K; k0 += 32) {
        #pragma unroll
        for (int i = 0; i < 4; i++) {
            int r = lr + i * 32;
            store_split<40>(Ah, Al, r, lc4, pa[i]);
            store_split<40>(Bh, Bl, r, lc4, pb[i]);
        }
        __syncthreads();

        if (k0 + 32 < K) {
            #pragma unroll
            for (int i = 0; i < 4; i++) {
                int r = lr + i * 32;
                pa[i] = *(const float4*)&A[(size_t)(row0 + r) * K + k0 + 32 + lc4 * 4];
                if (DUAL) {
                    float4 q = *(const float4*)&A2[(size_t)(row0 + r) * K + k0 + 32 + lc4 * 4];
                    pa[i].x += q.x; pa[i].y += q.y; pa[i].z += q.z; pa[i].w += q.w;
                }
                pb[i] = *(const float4*)&B[(size_t)(col0 + r) * K + k0 + 32 + lc4 * 4];
            }
        }

        #pragma unroll
        for (int ks = 0; ks < 2; ks++) {
            const int ka = ks * 16 + ((lane >> 4) << 3);
            uint32_t ah[4][4], al_[4][4];
            #pragma unroll
            for (int mi = 0; mi < 4; mi++) {
                int r = warp_m * 64 + mi * 16 + (lane & 15);
                LDSM_X4(ah[mi],  smem_u32(&Ah[r][ka]));
                LDSM_X4(al_[mi], smem_u32(&Al[r][ka]));
            }
            const int kb = ks * 16 + ((lane >> 3) & 1) * 8;
            uint32_t bh[4][2], bl_[4][2];
            #pragma unroll
            for (int ni = 0; ni < 4; ni++) {
                int r = warp_n * 32 + ni * 8 + (lane & 7);
                LDSM_X2(bh[ni],  smem_u32(&Bh[r][kb]));
                LDSM_X2(bl_[ni], smem_u32(&Bl[r][kb]));
            }
            #pragma unroll
            for (int mi = 0; mi < 4; mi++)
                #pragma unroll
                for (int ni = 0; ni < 4; ni++) {
                    MMA_BF16(acc[mi][ni], ah[mi],  bh[ni]);
                    MMA_BF16(acc[mi][ni], ah[mi],  bl_[ni]);
                    MMA_BF16(acc[mi][ni], al_[mi], bh[ni]);
                }
        }
        __syncthreads();
    }

    #pragma unroll
    for (int mi = 0; mi < 4; mi++) {
        int r0 = row0 + warp_m * 64 + mi * 16 + (lane >> 2);
        #pragma unroll
        for (int ni = 0; ni < 4; ni++) {
            int c = col0 + warp_n * 32 + ni * 8 + (lane & 3) * 2;
            float2 bv = *(const float2*)&bias[c];
            *(float2*)&C[(size_t)r0 * N + c] =
                make_float2(acc[mi][ni][0] + bv.x, acc[mi][ni][1] + bv.y);
            *(float2*)&C[(size_t)(r0 + 8) * N + c] =
                make_float2(acc[mi][ni][2] + bv.x, acc[mi][ni][3] + bv.y);
        }
    }
}

// =====================================================================
// Scores (HMMA): attw = exp((Q·K)/8) unnormalized + row partials.
// Whole K=64 in smem, one sync, 96 back-to-back MMAs. Grid: (16,16,32)
// =====================================================================
__global__ __launch_bounds__(256, 2) void mma_scores_kernel(float* __restrict__ attw)
{
    extern __shared__ __align__(16) uint16_t sm[];
    __shared__ float s_red[128][4];

    uint16_t (*Ah)[72] = (uint16_t(*)[72])sm;
    uint16_t (*Al)[72] = Ah + 128;
    uint16_t (*Bh)[72] = Al + 128;
    uint16_t (*Bl)[72] = Bh + 128;

    const int tid = threadIdx.x;
    const int lane = tid & 31, wid = tid >> 5;
    const int warp_m = wid >> 2, warp_n = wid & 3;
    const int bh = blockIdx.z;
    const int b = bh >> 4, h = bh & 15;
    const int row0 = blockIdx.y * 128, col0 = blockIdx.x * 128;

    const float* Qb = g_qkv + (size_t)b * SS * E3 + h * DH;
    const float* Kb = Qb + EB;

    #pragma unroll
    for (int i = 0; i < 8; i++) {
        int idx = tid + i * 256;
        int r = idx >> 4, c4 = idx & 15;
        float4 va = *(const float4*)&Qb[(size_t)(row0 + r) * E3 + c4 * 4];
        store_split<72>(Ah, Al, r, c4, va);
        float4 vb = *(const float4*)&Kb[(size_t)(col0 + r) * E3 + c4 * 4];
        store_split<72>(Bh, Bl, r, c4, vb);
    }
    __syncthreads();

    float acc[4][4][4];
    #pragma unroll
    for (int mi = 0; mi < 4; mi++)
        #pragma unroll
        for (int ni = 0; ni < 4; ni++)
            #pragma unroll
            for (int f = 0; f < 4; f++) acc[mi][ni][f] = 0.0f;

    #pragma unroll
    for (int c = 0; c < 2; c++) {
        #pragma unroll
        for (int ks = 0; ks < 2; ks++) {
            const int ka = c * 32 + ks * 16 + ((lane >> 4) << 3);
            uint32_t ah[4][4], al_[4][4];
            #pragma unroll
            for (int mi = 0; mi < 4; mi++) {
                int r = warp_m * 64 + mi * 16 + (lane & 15);
                LDSM_X4(ah[mi],  smem_u32(&Ah[r][ka]));
                LDSM_X4(al_[mi], smem_u32(&Al[r][ka]));
            }
            const int kb = c * 32 + ks * 16 + ((lane >> 3) & 1) * 8;
            uint32_t bh[4][2], bl_[4][2];
            #pragma unroll
            for (int ni = 0; ni < 4; ni++) {
                int r = warp_n * 32 + ni * 8 + (lane & 7);
                LDSM_X2(bh[ni],  smem_u32(&Bh[r][kb]));
                LDSM_X2(bl_[ni], smem_u32(&Bl[r][kb]));
            }
            #pragma unroll
            for (int mi = 0; mi < 4; mi++)
                #pragma unroll
                for (int ni = 0; ni < 4; ni++) {
                    MMA_BF16(acc[mi][ni], ah[mi],  bh[ni]);
                    MMA_BF16(acc[mi][ni], ah[mi],  bl_[ni]);
                    MMA_BF16(acc[mi][ni], al_[mi], bh[ni]);
                }
        }
    }

    float* Cb = attw + (size_t)bh * SS * SS;
    #pragma unroll
    for (int mi = 0; mi < 4; mi++) {
        int rl = warp_m * 64 + mi * 16 + (lane >> 2);
        float p_lo = 0.0f, p_hi = 0.0f;
        #pragma unroll
        for (int ni = 0; ni < 4; ni++) {
            int c = col0 + warp_n * 32 + ni * 8 + (lane & 3) * 2;
            float e0 = __expf(acc[mi][ni][0] * 0.125f);
            float e1 = __expf(acc[mi][ni][1] * 0.125f);
            float e2 = __expf(acc[mi][ni][2] * 0.125f);
            float e3 = __expf(acc[mi][ni][3] * 0.125f);
            *(float2*)&Cb[(size_t)(row0 + rl) * SS + c]     = make_float2(e0, e1);
            *(float2*)&Cb[(size_t)(row0 + rl + 8) * SS + c] = make_float2(e2, e3);
            p_lo += e0 + e1; p_hi += e2 + e3;
        }
        #pragma unroll
        for (int m = 1; m < 4; m <<= 1) {
            p_lo += __shfl_xor_sync(0xffffffffu, p_lo, m);
            p_hi += __shfl_xor_sync(0xffffffffu, p_hi, m);
        }
        if ((lane & 3) == 0) {
            s_red[rl][warp_n]     = p_lo;
            s_red[rl + 8][warp_n] = p_hi;
        }
    }
    __syncthreads();
    if (tid < 128) {
        float s = s_red[tid][0] + s_red[tid][1] + s_red[tid][2] + s_red[tid][3];
        g_part[((size_t)bh * SS + row0 + tid) * 16 + blockIdx.x] = s;
    }
}

// =====================================================================
// PV (HMMA), split-K x2, fused normalization + in-kernel rowsum fold.
// CTA 128x64 over K-half=1024. Grid: (16, 2, 32). Partial -> g_attn2[kh].
// =====================================================================
__global__ __launch_bounds__(256, 2) void mma_pv_kernel(float* __restrict__ attw)
{
    __shared__ __align__(16) uint16_t Ah[128][40];
    __shared__ __align__(16) uint16_t Al[128][40];
    __shared__ __align__(16) uint16_t Bh[32][72];
    __shared__ __align__(16) uint16_t Bl[32][72];
    __shared__ float s_inv[128];

    const int tid = threadIdx.x;
    const int lane = tid & 31, wid = tid >> 5;
    const int warp_m = wid >> 1, warp_n = wid & 1;
    const int bh = blockIdx.z;
    const int b = bh >> 4, h = bh & 15;
    const int row0 = blockIdx.x * 128;
    const int kh = blockIdx.y;                 // K-half index
    const int kbase = kh * (SS / 2);
    const int lr = tid >> 3, lc4 = tid & 7;
    const int vk = tid >> 4, vc4 = tid & 15;

    float* Pb = attw + (size_t)bh * SS * SS;
    const float* Vb = g_qkv + (size_t)b * SS * E3 + 2 * EB + h * DH;
    float* Ob = g_attn2[kh];

    // fold 16 col-block partials -> 1/rowsum (replaces fold kernel)
    if (tid < 128) {
        const float* p = &g_part[((size_t)bh * SS + row0 + tid) * 16];
        float s = 0.0f;
        #pragma unroll
        for (int i = 0; i < 16; i++) s += p[i];
        s_inv[tid] = 1.0f / s;
    }
    __syncthreads();

    float acc[2][4][4];
    #pragma unroll
    for (int mi = 0; mi < 2; mi++)
        #pragma unroll
        for (int ni = 0; ni < 4; ni++)
            #pragma unroll
            for (int f = 0; f < 4; f++) acc[mi][ni][f] = 0.0f;

    float4 pa[4], pv[2];
    #pragma unroll
    for (int i = 0; i < 4; i++)
        pa[i] = *(const float4*)&Pb[(size_t)(row0 + lr + i * 32) * SS + kbase + lc4 * 4];
    #pragma unroll
    for (int i = 0; i < 2; i++)
        pv[i] = *(const float4*)&Vb[(size_t)(kbase + vk + i * 16) * E3 + vc4 * 4];

    for (int k0 = kbase; k0 < kbase + SS / 2; k0 += 32) {
        #pragma unroll
        for (int i = 0; i < 4; i++) {
            int r = lr + i * 32;
            float inv = s_inv[r];
            float4 va = pa[i];
            va.x *= inv; va.y *= inv; va.z *= inv; va.w *= inv;
            *(float4*)&Pb[(size_t)(row0 + r) * SS + k0 + lc4 * 4] = va;  // normalized attw
            store_split<40>(Ah, Al, r, lc4, va);
        }
        #pragma unroll
        for (int i = 0; i < 2; i++)
            store_split<72>(Bh, Bl, vk + i * 16, vc4, pv[i]);
        __syncthreads();

        if (k0 + 32 < kbase + SS / 2) {
            #pragma unroll
            for (int i = 0; i < 4; i++)
                pa[i] = *(const float4*)&Pb[(size_t)(row0 + lr + i * 32) * SS + k0 + 32 + lc4 * 4];
            #pragma unroll
            for (int i = 0; i < 2; i++)
                pv[i] = *(const float4*)&Vb[(size_t)(k0 + 32 + vk + i * 16) * E3 + vc4 * 4];
        }

        #pragma unroll
        for (int ks = 0; ks < 2; ks++) {
            const int ka = ks * 16 + ((lane >> 4) << 3);
            uint32_t ah[2][4], al_[2][4];
            #pragma unroll
            for (int mi = 0; mi < 2; mi++) {
                int r = warp_m * 32 + mi * 16 + (lane & 15);
                LDSM_X4(ah[mi],  smem_u32(&Ah[r][ka]));
                LDSM_X4(al_[mi], smem_u32(&Al[r][ka]));
            }
            const int krow = ks * 16 + (lane & 15);
            uint32_t bh[4][2], bl_[4][2];
            #pragma unroll
            for (int ni = 0; ni < 4; ni++) {
                int n0 = warp_n * 32 + ni * 8;
                LDSM_X2_TRANS(bh[ni],  smem_u32(&Bh[krow][n0]));
                LDSM_X2_TRANS(bl_[ni], smem_u32(&Bl[krow][n0]));
            }
            #pragma unroll
            for (int mi = 0; mi < 2; mi++)
                #pragma unroll
                for (int ni = 0; ni < 4; ni++) {
                    MMA_BF16(acc[mi][ni], ah[mi],  bh[ni]);
                    MMA_BF16(acc[mi][ni], ah[mi],  bl_[ni]);
                    MMA_BF16(acc[mi][ni], al_[mi], bh[ni]);
                }
        }
        __syncthreads();
    }

    #pragma unroll
    for (int mi = 0; mi < 2; mi++) {
        int s0 = row0 + warp_m * 32 + mi * 16 + (lane >> 2);
        #pragma unroll
        for (int ni = 0; ni < 4; ni++) {
            int c = warp_n * 32 + ni * 8 + (lane & 3) * 2;
            float* o0 = &Ob[(size_t)(b * SS + s0) * EB + h * DH + c];
            float* o1 = &Ob[(size_t)(b * SS + s0 + 8) * EB + h * DH + c];
            *(float2*)o0 = make_float2(acc[mi][ni][0], acc[mi][ni][1]);
            *(float2*)o1 = make_float2(acc[mi][ni][2], acc[mi][ni][3]);
        }
    }
}

// =====================================================================
extern "C" void kernel_launch(void* const* d_in, const int* in_sizes, int n_in,
                              void* d_out, int out_size)
{
    (void)in_sizes; (void)n_in; (void)out_size;
    const float* x     = (const float*)d_in[0];
    const float* qkv_w = (const float*)d_in[1];
    const float* qkv_b = (const float*)d_in[2];
    const float* out_w = (const float*)d_in[3];
    const float* out_b = (const float*)d_in[4];

    float* out  = (float*)d_out;                  // output: [2,2048,1024]
    float* attw = out + (size_t)MT * EB;          // attn_weights: [2,16,2048,2048]

    float* d_qkv = nullptr;
    float* d_at2 = nullptr;
    cudaGetSymbolAddress((void**)&d_qkv, g_qkv);
    cudaGetSymbolAddress((void**)&d_at2, g_attn2);

    cudaFuncSetAttribute(mma_scores_kernel, cudaFuncAttributeMaxDynamicSharedMemorySize, SC_SMEM);

    // 1. QKV projection
    {
        dim3 grid(E3 / 128, MT / 128);
        mma_gemm_bias_nt<false><<<grid, 256>>>(x, nullptr, qkv_w, qkv_b, d_qkv, MT, E3, EB);
    }
    // 2. scores + exp + row partials
    {
        dim3 grid(SS / 128, SS / 128, BB * HN);
        mma_scores_kernel<<<grid, 256, SC_SMEM>>>(attw);
    }
    // 3. P @ V split-K x2 with fused normalization + rowsum fold
    {
        dim3 grid(SS / 128, 2, BB * HN);
        mma_pv_kernel<<<grid, 256>>>(attw);
    }
    // 4. out projection (sums the two PV partials at A-load)
    {
        dim3 grid(EB / 128, MT / 128);
        mma_gemm_bias_nt<true><<<grid, 256>>>(d_at2, d_at2 + (size_t)MT * EB,
                                              out_w, out_b, out, MT, EB, EB);
    }
}

// round 17
// speedup vs baseline: 1.0259x; 1.0259x over previous
#include <cuda_runtime.h>
#include <cuda_bf16.h>
#include <cstdint>

#define EB    1024
#define HN    16
#define DH    64
#define BB    2
#define SS    2048
#define MT    (BB*SS)       // 4096
#define E3    (3*EB)        // 3072

typedef unsigned long long u64;

// Scratch (device globals — allocation is forbidden)
__device__ float g_qkv[(size_t)MT * E3];      // [token][3E]
__device__ float g_attn[(size_t)MT * EB];     // [token][E]
__device__ float g_rowsum[BB * HN * SS];
__device__ float g_part[(size_t)BB * HN * SS * 16];

// ---------------- HMMA (mma.sync) helpers — sm_80-era PTX ----------------
__device__ __forceinline__ uint32_t smem_u32(const void* p) {
    uint32_t a;
    asm("{ .reg .u64 t; cvta.to.shared.u64 t, %1; cvt.u32.u64 %0, t; }" : "=r"(a) : "l"(p));
    return a;
}
#define LDSM_X4(r, addr) \
    asm volatile("ldmatrix.sync.aligned.m8n8.x4.shared.b16 {%0,%1,%2,%3}, [%4];" \
        : "=r"((r)[0]), "=r"((r)[1]), "=r"((r)[2]), "=r"((r)[3]) : "r"(addr))
#define LDSM_X2(r, addr) \
    asm volatile("ldmatrix.sync.aligned.m8n8.x2.shared.b16 {%0,%1}, [%2];" \
        : "=r"((r)[0]), "=r"((r)[1]) : "r"(addr))
#define LDSM_X2_TRANS(r, addr) \
    asm volatile("ldmatrix.sync.aligned.m8n8.x2.trans.shared.b16 {%0,%1}, [%2];" \
        : "=r"((r)[0]), "=r"((r)[1]) : "r"(addr))
#define MMA_BF16(d, a, b) \
    asm volatile("mma.sync.aligned.m16n8k16.row.col.f32.bf16.bf16.f32 " \
        "{%0,%1,%2,%3}, {%4,%5,%6,%7}, {%8,%9}, {%0,%1,%2,%3};" \
        : "+f"((d)[0]), "+f"((d)[1]), "+f"((d)[2]), "+f"((d)[3]) \
        : "r"((a)[0]), "r"((a)[1]), "r"((a)[2]), "r"((a)[3]), \
          "r"((b)[0]), "r"((b)[1]))

// split two fp32 into bf16-hi pair and bf16-lo pair (packed u32: lo half = x0)
__device__ __forceinline__ void split2(float x0, float x1, uint32_t& hi2, uint32_t& lo2) {
    asm("cvt.rn.bf16x2.f32 %0, %1, %2;" : "=r"(hi2) : "f"(x1), "f"(x0));
    float h0 = __uint_as_float(hi2 << 16);
    float h1 = __uint_as_float(hi2 & 0xFFFF0000u);
    float r0 = x0 - h0, r1 = x1 - h1;
    asm("cvt.rn.bf16x2.f32 %0, %1, %2;" : "=r"(lo2) : "f"(r1), "f"(r0));
}

template<int W>
__device__ __forceinline__ void store_split(uint16_t (*H)[W], uint16_t (*L)[W],
                                            int r, int c4, float4 v) {
    uint32_t h0, l0, h1, l1;
    split2(v.x, v.y, h0, l0); split2(v.z, v.w, h1, l1);
    *(uint32_t*)&H[r][c4 * 4]     = h0; *(uint32_t*)&H[r][c4 * 4 + 2] = h1;
    *(uint32_t*)&L[r][c4 * 4]     = l0; *(uint32_t*)&L[r][c4 * 4 + 2] = l1;
}

#define SC_SMEM (4 * 128 * 72 * 2)     // 73728 bytes (scores whole-K tiles)

// =====================================================================
// HMMA GEMM: C[M,N] = A[M,K] @ B[N,K]^T + bias[N]
// CTA 128x128, BK=32, 8 warps (2m x 4n), register-prefetch pipelined.
// MMA passes reordered: all hh, then hl, then lh (break acc chains).
// =====================================================================
__global__ __launch_bounds__(256, 2) void mma_gemm_bias_nt(
    const float* __restrict__ A, const float* __restrict__ B,
    const float* __restrict__ bias, float* __restrict__ C,
    int M, int N, int K)
{
    __shared__ __align__(16) uint16_t Ah[128][40];
    __shared__ __align__(16) uint16_t Al[128][40];
    __shared__ __align__(16) uint16_t Bh[128][40];
    __shared__ __align__(16) uint16_t Bl[128][40];

    const int tid = threadIdx.x;
    const int lane = tid & 31, wid = tid >> 5;
    const int warp_m = wid >> 2, warp_n = wid & 3;
    const int row0 = blockIdx.y * 128, col0 = blockIdx.x * 128;
    const int lr = tid >> 3, lc4 = tid & 7;

    float acc[4][4][4];
    #pragma unroll
    for (int mi = 0; mi < 4; mi++)
        #pragma unroll
        for (int ni = 0; ni < 4; ni++)
            #pragma unroll
            for (int f = 0; f < 4; f++) acc[mi][ni][f] = 0.0f;

    float4 pa[4], pb[4];
    #pragma unroll
    for (int i = 0; i < 4; i++) {
        int r = lr + i * 32;
        pa[i] = *(const float4*)&A[(size_t)(row0 + r) * K + lc4 * 4];
        pb[i] = *(const float4*)&B[(size_t)(col0 + r) * K + lc4 * 4];
    }

    for (int k0 = 0; k0 < K; k0 += 32) {
        #pragma unroll
        for (int i = 0; i < 4; i++) {
            int r = lr + i * 32;
            store_split<40>(Ah, Al, r, lc4, pa[i]);
            store_split<40>(Bh, Bl, r, lc4, pb[i]);
        }
        __syncthreads();

        if (k0 + 32 < K) {
            #pragma unroll
            for (int i = 0; i < 4; i++) {
                int r = lr + i * 32;
                pa[i] = *(const float4*)&A[(size_t)(row0 + r) * K + k0 + 32 + lc4 * 4];
                pb[i] = *(const float4*)&B[(size_t)(col0 + r) * K + k0 + 32 + lc4 * 4];
            }
        }

        #pragma unroll
        for (int ks = 0; ks < 2; ks++) {
            const int ka = ks * 16 + ((lane >> 4) << 3);
            uint32_t ah[4][4], al_[4][4];
            #pragma unroll
            for (int mi = 0; mi < 4; mi++) {
                int r = warp_m * 64 + mi * 16 + (lane & 15);
                LDSM_X4(ah[mi],  smem_u32(&Ah[r][ka]));
                LDSM_X4(al_[mi], smem_u32(&Al[r][ka]));
            }
            const int kb = ks * 16 + ((lane >> 3) & 1) * 8;
            uint32_t bh[4][2], bl_[4][2];
            #pragma unroll
            for (int ni = 0; ni < 4; ni++) {
                int r = warp_n * 32 + ni * 8 + (lane & 7);
                LDSM_X2(bh[ni],  smem_u32(&Bh[r][kb]));
                LDSM_X2(bl_[ni], smem_u32(&Bl[r][kb]));
            }
            // pass 1: hh (16 independent MMAs)
            #pragma unroll
            for (int mi = 0; mi < 4; mi++)
                #pragma unroll
                for (int ni = 0; ni < 4; ni++)
                    MMA_BF16(acc[mi][ni], ah[mi], bh[ni]);
            // pass 2: hl
            #pragma unroll
            for (int mi = 0; mi < 4; mi++)
                #pragma unroll
                for (int ni = 0; ni < 4; ni++)
                    MMA_BF16(acc[mi][ni], ah[mi], bl_[ni]);
            // pass 3: lh
            #pragma unroll
            for (int mi = 0; mi < 4; mi++)
                #pragma unroll
                for (int ni = 0; ni < 4; ni++)
                    MMA_BF16(acc[mi][ni], al_[mi], bh[ni]);
        }
        __syncthreads();
    }

    #pragma unroll
    for (int mi = 0; mi < 4; mi++) {
        int r0 = row0 + warp_m * 64 + mi * 16 + (lane >> 2);
        #pragma unroll
        for (int ni = 0; ni < 4; ni++) {
            int c = col0 + warp_n * 32 + ni * 8 + (lane & 3) * 2;
            float2 bv = *(const float2*)&bias[c];
            *(float2*)&C[(size_t)r0 * N + c] =
                make_float2(acc[mi][ni][0] + bv.x, acc[mi][ni][1] + bv.y);
            *(float2*)&C[(size_t)(r0 + 8) * N + c] =
                make_float2(acc[mi][ni][2] + bv.x, acc[mi][ni][3] + bv.y);
        }
    }
}

// =====================================================================
// Scores (HMMA): attw = exp((Q·K)/8) unnormalized + row partials.
// Whole K=64 in smem, one sync; MMA passes reordered. Grid: (16,16,32)
// =====================================================================
__global__ __launch_bounds__(256, 2) void mma_scores_kernel(float* __restrict__ attw)
{
    extern __shared__ __align__(16) uint16_t sm[];
    __shared__ float s_red[128][4];

    uint16_t (*Ah)[72] = (uint16_t(*)[72])sm;
    uint16_t (*Al)[72] = Ah + 128;
    uint16_t (*Bh)[72] = Al + 128;
    uint16_t (*Bl)[72] = Bh + 128;

    const int tid = threadIdx.x;
    const int lane = tid & 31, wid = tid >> 5;
    const int warp_m = wid >> 2, warp_n = wid & 3;
    const int bh = blockIdx.z;
    const int b = bh >> 4, h = bh & 15;
    const int row0 = blockIdx.y * 128, col0 = blockIdx.x * 128;

    const float* Qb = g_qkv + (size_t)b * SS * E3 + h * DH;
    const float* Kb = Qb + EB;

    #pragma unroll
    for (int i = 0; i < 8; i++) {
        int idx = tid + i * 256;
        int r = idx >> 4, c4 = idx & 15;
        float4 va = *(const float4*)&Qb[(size_t)(row0 + r) * E3 + c4 * 4];
        store_split<72>(Ah, Al, r, c4, va);
        float4 vb = *(const float4*)&Kb[(size_t)(col0 + r) * E3 + c4 * 4];
        store_split<72>(Bh, Bl, r, c4, vb);
    }
    __syncthreads();

    float acc[4][4][4];
    #pragma unroll
    for (int mi = 0; mi < 4; mi++)
        #pragma unroll
        for (int ni = 0; ni < 4; ni++)
            #pragma unroll
            for (int f = 0; f < 4; f++) acc[mi][ni][f] = 0.0f;

    #pragma unroll
    for (int c = 0; c < 2; c++) {
        #pragma unroll
        for (int ks = 0; ks < 2; ks++) {
            const int ka = c * 32 + ks * 16 + ((lane >> 4) << 3);
            uint32_t ah[4][4], al_[4][4];
            #pragma unroll
            for (int mi = 0; mi < 4; mi++) {
                int r = warp_m * 64 + mi * 16 + (lane & 15);
                LDSM_X4(ah[mi],  smem_u32(&Ah[r][ka]));
                LDSM_X4(al_[mi], smem_u32(&Al[r][ka]));
            }
            const int kb = c * 32 + ks * 16 + ((lane >> 3) & 1) * 8;
            uint32_t bh[4][2], bl_[4][2];
            #pragma unroll
            for (int ni = 0; ni < 4; ni++) {
                int r = warp_n * 32 + ni * 8 + (lane & 7);
                LDSM_X2(bh[ni],  smem_u32(&Bh[r][kb]));
                LDSM_X2(bl_[ni], smem_u32(&Bl[r][kb]));
            }
            #pragma unroll
            for (int mi = 0; mi < 4; mi++)
                #pragma unroll
                for (int ni = 0; ni < 4; ni++)
                    MMA_BF16(acc[mi][ni], ah[mi], bh[ni]);
            #pragma unroll
            for (int mi = 0; mi < 4; mi++)
                #pragma unroll
                for (int ni = 0; ni < 4; ni++)
                    MMA_BF16(acc[mi][ni], ah[mi], bl_[ni]);
            #pragma unroll
            for (int mi = 0; mi < 4; mi++)
                #pragma unroll
                for (int ni = 0; ni < 4; ni++)
                    MMA_BF16(acc[mi][ni], al_[mi], bh[ni]);
        }
    }

    float* Cb = attw + (size_t)bh * SS * SS;
    #pragma unroll
    for (int mi = 0; mi < 4; mi++) {
        int rl = warp_m * 64 + mi * 16 + (lane >> 2);
        float p_lo = 0.0f, p_hi = 0.0f;
        #pragma unroll
        for (int ni = 0; ni < 4; ni++) {
            int c = col0 + warp_n * 32 + ni * 8 + (lane & 3) * 2;
            float e0 = __expf(acc[mi][ni][0] * 0.125f);
            float e1 = __expf(acc[mi][ni][1] * 0.125f);
            float e2 = __expf(acc[mi][ni][2] * 0.125f);
            float e3 = __expf(acc[mi][ni][3] * 0.125f);
            *(float2*)&Cb[(size_t)(row0 + rl) * SS + c]     = make_float2(e0, e1);
            *(float2*)&Cb[(size_t)(row0 + rl + 8) * SS + c] = make_float2(e2, e3);
            p_lo += e0 + e1; p_hi += e2 + e3;
        }
        #pragma unroll
        for (int m = 1; m < 4; m <<= 1) {
            p_lo += __shfl_xor_sync(0xffffffffu, p_lo, m);
            p_hi += __shfl_xor_sync(0xffffffffu, p_hi, m);
        }
        if ((lane & 3) == 0) {
            s_red[rl][warp_n]     = p_lo;
            s_red[rl + 8][warp_n] = p_hi;
        }
    }
    __syncthreads();
    if (tid < 128) {
        float s = s_red[tid][0] + s_red[tid][1] + s_red[tid][2] + s_red[tid][3];
        g_part[((size_t)bh * SS + row0 + tid) * 16 + blockIdx.x] = s;
    }
}

// =====================================================================
// Fold 16 col-block partials per row -> g_rowsum.
// =====================================================================
__global__ __launch_bounds__(256) void rowsum_fold_kernel()
{
    int row = blockIdx.x * 256 + threadIdx.x;
    const float* p = &g_part[(size_t)row * 16];
    float s = 0.0f;
    #pragma unroll
    for (int i = 0; i < 16; i++) s += p[i];
    g_rowsum[row] = s;
}

// =====================================================================
// PV (HMMA) fused normalization, register-prefetch pipelined.
// CTA 128x64, BK=32, 8 warps (4m x 2n), MMA passes reordered.
// Grid: (16, 1, 32)
// =====================================================================
__global__ __launch_bounds__(256, 2) void mma_pv_kernel(float* __restrict__ attw)
{
    __shared__ __align__(16) uint16_t Ah[128][40];
    __shared__ __align__(16) uint16_t Al[128][40];
    __shared__ __align__(16) uint16_t Bh[32][72];
    __shared__ __align__(16) uint16_t Bl[32][72];
    __shared__ float s_inv[128];

    const int tid = threadIdx.x;
    const int lane = tid & 31, wid = tid >> 5;
    const int warp_m = wid >> 1, warp_n = wid & 1;
    const int bh = blockIdx.z;
    const int b = bh >> 4, h = bh & 15;
    const int row0 = blockIdx.x * 128;
    const int lr = tid >> 3, lc4 = tid & 7;
    const int vk = tid >> 4, vc4 = tid & 15;

    float* Pb = attw + (size_t)bh * SS * SS;
    const float* Vb = g_qkv + (size_t)b * SS * E3 + 2 * EB + h * DH;

    if (tid < 128)
        s_inv[tid] = 1.0f / g_rowsum[(size_t)bh * SS + row0 + tid];
    __syncthreads();

    float acc[2][4][4];
    #pragma unroll
    for (int mi = 0; mi < 2; mi++)
        #pragma unroll
        for (int ni = 0; ni < 4; ni++)
            #pragma unroll
            for (int f = 0; f < 4; f++) acc[mi][ni][f] = 0.0f;

    float4 pa[4], pv[2];
    #pragma unroll
    for (int i = 0; i < 4; i++)
        pa[i] = *(const float4*)&Pb[(size_t)(row0 + lr + i * 32) * SS + lc4 * 4];
    #pragma unroll
    for (int i = 0; i < 2; i++)
        pv[i] = *(const float4*)&Vb[(size_t)(vk + i * 16) * E3 + vc4 * 4];

    for (int k0 = 0; k0 < SS; k0 += 32) {
        #pragma unroll
        for (int i = 0; i < 4; i++) {
            int r = lr + i * 32;
            float inv = s_inv[r];
            float4 va = pa[i];
            va.x *= inv; va.y *= inv; va.z *= inv; va.w *= inv;
            *(float4*)&Pb[(size_t)(row0 + r) * SS + k0 + lc4 * 4] = va;  // normalized attw
            store_split<40>(Ah, Al, r, lc4, va);
        }
        #pragma unroll
        for (int i = 0; i < 2; i++)
            store_split<72>(Bh, Bl, vk + i * 16, vc4, pv[i]);
        __syncthreads();

        if (k0 + 32 < SS) {
            #pragma unroll
            for (int i = 0; i < 4; i++)
                pa[i] = *(const float4*)&Pb[(size_t)(row0 + lr + i * 32) * SS + k0 + 32 + lc4 * 4];
            #pragma unroll
            for (int i = 0; i < 2; i++)
                pv[i] = *(const float4*)&Vb[(size_t)(k0 + 32 + vk + i * 16) * E3 + vc4 * 4];
        }

        #pragma unroll
        for (int ks = 0; ks < 2; ks++) {
            const int ka = ks * 16 + ((lane >> 4) << 3);
            uint32_t ah[2][4], al_[2][4];
            #pragma unroll
            for (int mi = 0; mi < 2; mi++) {
                int r = warp_m * 32 + mi * 16 + (lane & 15);
                LDSM_X4(ah[mi],  smem_u32(&Ah[r][ka]));
                LDSM_X4(al_[mi], smem_u32(&Al[r][ka]));
            }
            const int krow = ks * 16 + (lane & 15);
            uint32_t bh[4][2], bl_[4][2];
            #pragma unroll
            for (int ni = 0; ni < 4; ni++) {
                int n0 = warp_n * 32 + ni * 8;
                LDSM_X2_TRANS(bh[ni],  smem_u32(&Bh[krow][n0]));
                LDSM_X2_TRANS(bl_[ni], smem_u32(&Bl[krow][n0]));
            }
            #pragma unroll
            for (int mi = 0; mi < 2; mi++)
                #pragma unroll
                for (int ni = 0; ni < 4; ni++)
                    MMA_BF16(acc[mi][ni], ah[mi], bh[ni]);
            #pragma unroll
            for (int mi = 0; mi < 2; mi++)
                #pragma unroll
                for (int ni = 0; ni < 4; ni++)
                    MMA_BF16(acc[mi][ni], ah[mi], bl_[ni]);
            #pragma unroll
            for (int mi = 0; mi < 2; mi++)
                #pragma unroll
                for (int ni = 0; ni < 4; ni++)
                    MMA_BF16(acc[mi][ni], al_[mi], bh[ni]);
        }
        __syncthreads();
    }

    #pragma unroll
    for (int mi = 0; mi < 2; mi++) {
        int s0 = row0 + warp_m * 32 + mi * 16 + (lane >> 2);
        #pragma unroll
        for (int ni = 0; ni < 4; ni++) {
            int c = warp_n * 32 + ni * 8 + (lane & 3) * 2;
            float* o0 = &g_attn[(size_t)(b * SS + s0) * EB + h * DH + c];
            float* o1 = &g_attn[(size_t)(b * SS + s0 + 8) * EB + h * DH + c];
            *(float2*)o0 = make_float2(acc[mi][ni][0], acc[mi][ni][1]);
            *(float2*)o1 = make_float2(acc[mi][ni][2], acc[mi][ni][3]);
        }
    }
}

// =====================================================================
extern "C" void kernel_launch(void* const* d_in, const int* in_sizes, int n_in,
                              void* d_out, int out_size)
{
    (void)in_sizes; (void)n_in; (void)out_size;
    const float* x     = (const float*)d_in[0];
    const float* qkv_w = (const float*)d_in[1];
    const float* qkv_b = (const float*)d_in[2];
    const float* out_w = (const float*)d_in[3];
    const float* out_b = (const float*)d_in[4];

    float* out  = (float*)d_out;                  // output: [2,2048,1024]
    float* attw = out + (size_t)MT * EB;          // attn_weights: [2,16,2048,2048]

    float* d_qkv  = nullptr;
    float* d_attn = nullptr;
    cudaGetSymbolAddress((void**)&d_qkv,  g_qkv);
    cudaGetSymbolAddress((void**)&d_attn, g_attn);

    cudaFuncSetAttribute(mma_scores_kernel, cudaFuncAttributeMaxDynamicSharedMemorySize, SC_SMEM);

    // 1. QKV projection
    {
        dim3 grid(E3 / 128, MT / 128);
        mma_gemm_bias_nt<<<grid, 256>>>(x, qkv_w, qkv_b, d_qkv, MT, E3, EB);
    }
    // 2. scores + exp + row partials
    {
        dim3 grid(SS / 128, SS / 128, BB * HN);
        mma_scores_kernel<<<grid, 256, SC_SMEM>>>(attw);
    }
    // 3. fold partials
    rowsum_fold_kernel<<<BB * HN * SS / 256, 256>>>();
    // 4. P @ V with fused normalization
    {
        dim3 grid(SS / 128, 1, BB * HN);
        mma_pv_kernel<<<grid, 256>>>(attw);
    }
    // 5. out projection
    {
        dim3 grid(EB / 128, MT / 128);
        mma_gemm_bias_nt<<<grid, 256>>>(d_attn, out_w, out_b, out, MT, EB, EB);
    }
}